// round 1
// baseline (speedup 1.0000x reference)
#include <cuda_runtime.h>
#include <math.h>
#include <stdint.h>

#define NB   64
#define CIN  256
#define COUT 256
#define HH   56
#define WWID 56
#define HW   (HH * WWID)       // 3136
#define NWORDS 8               // CIN / 32
#define TAPS 9
#define WPC  (TAPS * NWORDS)   // 72 words per output channel
#define EPSC 1e-5

// Scratch (allocation-free rule: __device__ globals)
__device__ float        g_scale[CIN];
__device__ float        g_shift[CIN];
__device__ unsigned int g_xbits[(size_t)NB * HW * NWORDS];   // [n][h][w][word]  ~6.4 MB
__device__ unsigned int g_wbits[COUT * WPC];                 // [co][tap][word]
__device__ int          g_w9[COUT * TAPS];                   // popc of each weight tap word-group

// ---------------------------------------------------------------------------
// 1) BatchNorm statistics per channel (double accumulation for accuracy).
//    Produces scale[c] = gamma*rstd, shift[c] = beta - mean*scale.
// ---------------------------------------------------------------------------
__global__ void bn_stats_kernel(const float* __restrict__ x,
                                const float* __restrict__ gamma,
                                const float* __restrict__ beta) {
    const int c = blockIdx.x;
    double s = 0.0, s2 = 0.0;
    const float* xc = x + (size_t)c * HW;
    for (int n = 0; n < NB; ++n) {
        const float* p = xc + (size_t)n * CIN * HW;
        for (int i = threadIdx.x; i < HW; i += blockDim.x) {
            float v = p[i];
            s  += (double)v;
            s2 += (double)v * (double)v;
        }
    }
    __shared__ double ws[32], ws2[32];
    #pragma unroll
    for (int o = 16; o > 0; o >>= 1) {
        s  += __shfl_down_sync(0xffffffffu, s,  o);
        s2 += __shfl_down_sync(0xffffffffu, s2, o);
    }
    const int warp = threadIdx.x >> 5, lane = threadIdx.x & 31;
    if (lane == 0) { ws[warp] = s; ws2[warp] = s2; }
    __syncthreads();
    if (warp == 0) {
        const int nw = blockDim.x >> 5;
        s  = (lane < nw) ? ws[lane]  : 0.0;
        s2 = (lane < nw) ? ws2[lane] : 0.0;
        #pragma unroll
        for (int o = 16; o > 0; o >>= 1) {
            s  += __shfl_down_sync(0xffffffffu, s,  o);
            s2 += __shfl_down_sync(0xffffffffu, s2, o);
        }
        if (lane == 0) {
            const double Nt = (double)NB * (double)HW;
            double mean = s / Nt;
            double var  = s2 / Nt - mean * mean;
            float rstd  = (float)(1.0 / sqrt(var + EPSC));
            float sc    = rstd * gamma[c];
            g_scale[c] = sc;
            g_shift[c] = beta[c] - (float)mean * sc;
        }
    }
}

// ---------------------------------------------------------------------------
// 2) Binarize + bit-pack activations: bit=1 iff BN(x) > 0.
//    Layout: g_xbits[(n*HW + s)*8 + word], bit j of word = channel word*32+j.
// ---------------------------------------------------------------------------
__global__ void pack_x_kernel(const float* __restrict__ x) {
    const int idx = blockIdx.x * blockDim.x + threadIdx.x; // NB*8*HW threads
    if (idx >= NB * NWORDS * HW) return;
    const int s    = idx % HW;
    const int t    = idx / HW;
    const int word = t & 7;
    const int n    = t >> 3;
    const int cbase = word * 32;
    const float* p = x + ((size_t)(n * CIN + cbase)) * HW + s;
    unsigned int bits = 0;
    #pragma unroll
    for (int j = 0; j < 32; ++j) {
        float v  = p[(size_t)j * HW];
        float xh = fmaf(v, g_scale[cbase + j], g_shift[cbase + j]);
        if (xh > 0.0f) bits |= (1u << j);
    }
    g_xbits[((size_t)n * HW + s) * NWORDS + word] = bits;
}

// ---------------------------------------------------------------------------
// 3) Bit-pack weights (bit=1 iff w > 0) + per-(co,tap) popcount table.
//    w layout: [co][ci][kh][kw]  (tap = kh*3+kw, stride between ci is 9).
// ---------------------------------------------------------------------------
__global__ void pack_w_kernel(const float* __restrict__ w) {
    const int idx = blockIdx.x * blockDim.x + threadIdx.x; // COUT*9*8 = 18432
    if (idx >= COUT * TAPS * NWORDS) return;
    const int word = idx & 7;
    const int tap  = (idx >> 3) % TAPS;
    const int co   = idx / (TAPS * NWORDS);
    const float* p = w + ((size_t)co * CIN + word * 32) * TAPS + tap;
    unsigned int bits = 0;
    #pragma unroll
    for (int j = 0; j < 32; ++j)
        if (p[(size_t)j * TAPS] > 0.0f) bits |= (1u << j);
    g_wbits[co * WPC + tap * NWORDS + word] = bits;
    int pc = __popc(bits);
    #pragma unroll
    for (int o = 4; o > 0; o >>= 1)            // reduce over the 8 word-lanes
        pc += __shfl_down_sync(0xffffffffu, pc, o, 8);
    if (word == 0) g_w9[co * TAPS + tap] = pc;
}

// ---------------------------------------------------------------------------
// 4) XNOR-popcount conv + bias + ReLU.
//    Block: 224 threads = (56 w) x (4 h rows) for one n; loops all 256 co.
//    x window (72 words) lives in registers; all weights (73 KB) in smem.
// ---------------------------------------------------------------------------
#define CONV_THREADS 224
#define SMEM_CONV ((COUT * WPC + COUT * TAPS + COUT) * 4)

__global__ void __launch_bounds__(CONV_THREADS, 2)
bconv_kernel(const float* __restrict__ bias, float* __restrict__ out) {
    extern __shared__ unsigned int smem[];
    unsigned int* s_w   = smem;                       // COUT*72
    int*          s_w9  = (int*)(smem + COUT * WPC);  // COUT*9
    float*        s_b   = (float*)(smem + COUT * WPC + COUT * TAPS); // COUT

    const int tid = threadIdx.x;
    for (int i = tid; i < COUT * WPC; i += CONV_THREADS) s_w[i] = g_wbits[i];
    for (int i = tid; i < COUT * TAPS; i += CONV_THREADS) s_w9[i] = g_w9[i];
    for (int i = tid; i < COUT; i += CONV_THREADS) s_b[i] = bias[i];
    __syncthreads();

    const int tx = tid % WWID;       // output w
    const int ty = tid / WWID;       // 0..3
    const int h  = blockIdx.x * 4 + ty;
    const int n  = blockIdx.y;

    const unsigned int* xb = g_xbits + (size_t)n * HW * NWORDS;

    unsigned int xr[WPC];
    unsigned int invmask = 0;
    #pragma unroll
    for (int dh = -1; dh <= 1; ++dh) {
        #pragma unroll
        for (int dw = -1; dw <= 1; ++dw) {
            const int tap = (dh + 1) * 3 + (dw + 1);
            const int hh = h + dh, ww = tx + dw;
            const bool valid = (hh >= 0) & (hh < HH) & (ww >= 0) & (ww < WWID);
            if (valid) {
                const uint4* p = (const uint4*)(xb + ((size_t)hh * WWID + ww) * NWORDS);
                uint4 a = p[0], b2 = p[1];
                xr[tap*8+0]=a.x;  xr[tap*8+1]=a.y;  xr[tap*8+2]=a.z;  xr[tap*8+3]=a.w;
                xr[tap*8+4]=b2.x; xr[tap*8+5]=b2.y; xr[tap*8+6]=b2.z; xr[tap*8+7]=b2.w;
            } else {
                invmask |= (1u << tap);
                #pragma unroll
                for (int k = 0; k < 8; ++k) xr[tap*8+k] = 0u;
            }
        }
    }
    const int nvalid = TAPS - __popc(invmask);
    const int base   = CIN * nvalid;

    float* outp = out + (size_t)n * COUT * HW + h * WWID + tx;

    #pragma unroll 2
    for (int co = 0; co < COUT; ++co) {
        const unsigned int* wp = s_w + co * WPC;
        int acc = 0;
        #pragma unroll
        for (int t = 0; t < WPC; ++t)
            acc += __popc(xr[t] ^ wp[t]);
        int corr = 0;
        if (invmask) {
            unsigned int m = invmask;
            while (m) {
                const int tap = __ffs(m) - 1;
                m &= m - 1;
                corr += s_w9[co * TAPS + tap];
            }
        }
        float y = (float)(base - 2 * acc + 2 * corr) + s_b[co];
        outp[(size_t)co * HW] = fmaxf(y, 0.0f);
    }
}

// ---------------------------------------------------------------------------
extern "C" void kernel_launch(void* const* d_in, const int* in_sizes, int n_in,
                              void* d_out, int out_size) {
    const float* x     = (const float*)d_in[0];
    const float* gamma = (const float*)d_in[1];
    const float* beta  = (const float*)d_in[2];
    const float* w     = (const float*)d_in[3];
    const float* b     = (const float*)d_in[4];
    float* out = (float*)d_out;

    bn_stats_kernel<<<CIN, 1024>>>(x, gamma, beta);

    const int px_threads = NB * NWORDS * HW;
    pack_x_kernel<<<(px_threads + 255) / 256, 256>>>(x);

    pack_w_kernel<<<(COUT * TAPS * NWORDS + 255) / 256, 256>>>(w);

    cudaFuncSetAttribute(bconv_kernel,
                         cudaFuncAttributeMaxDynamicSharedMemorySize, SMEM_CONV);
    dim3 grid(HH / 4, NB);
    bconv_kernel<<<grid, CONV_THREADS, SMEM_CONV>>>(b, out);
}

// round 2
// speedup vs baseline: 1.7672x; 1.7672x over previous
#include <cuda_runtime.h>
#include <math.h>
#include <stdint.h>

#define NB   64
#define CIN  256
#define COUT 256
#define HH   56
#define WWID 56
#define HW   (HH * WWID)       // 3136
#define NWORDS 8               // CIN / 32
#define TAPS 9
#define WPC  (TAPS * NWORDS)   // 72 words per output channel
#define EPSC 1e-5
#define NSLICE 8               // batch slices for bn stats stage 1

// Scratch (allocation-free rule: __device__ globals)
__device__ float        g_scale[CIN];
__device__ float        g_shift[CIN];
__device__ double       g_part[CIN * NSLICE * 2];            // partial sums (s, s2)
__device__ unsigned int g_xbits[(size_t)NB * HW * NWORDS];   // [n][h][w][word]  ~6.4 MB
__device__ unsigned int g_wbits[COUT * WPC];                 // [co][tap][word]
__device__ int          g_w9[COUT * TAPS];                   // popc of weight tap word-group

// ---------------------------------------------------------------------------
// 1a) BN stats stage 1: per (channel, batch-slice) partial sums (double).
// ---------------------------------------------------------------------------
__global__ void bn_stats1_kernel(const float* __restrict__ x) {
    const int c     = blockIdx.x;
    const int slice = blockIdx.y;
    const int nper  = NB / NSLICE;
    double s = 0.0, s2 = 0.0;
    for (int n = slice * nper; n < (slice + 1) * nper; ++n) {
        const float* p = x + ((size_t)n * CIN + c) * HW;
        for (int i = threadIdx.x; i < HW; i += blockDim.x) {
            float v = p[i];
            s  += (double)v;
            s2 += (double)v * (double)v;
        }
    }
    __shared__ double ws[32], ws2[32];
    #pragma unroll
    for (int o = 16; o > 0; o >>= 1) {
        s  += __shfl_down_sync(0xffffffffu, s,  o);
        s2 += __shfl_down_sync(0xffffffffu, s2, o);
    }
    const int warp = threadIdx.x >> 5, lane = threadIdx.x & 31;
    if (lane == 0) { ws[warp] = s; ws2[warp] = s2; }
    __syncthreads();
    if (warp == 0) {
        const int nw = blockDim.x >> 5;
        s  = (lane < nw) ? ws[lane]  : 0.0;
        s2 = (lane < nw) ? ws2[lane] : 0.0;
        #pragma unroll
        for (int o = 16; o > 0; o >>= 1) {
            s  += __shfl_down_sync(0xffffffffu, s,  o);
            s2 += __shfl_down_sync(0xffffffffu, s2, o);
        }
        if (lane == 0) {
            g_part[(c * NSLICE + slice) * 2 + 0] = s;
            g_part[(c * NSLICE + slice) * 2 + 1] = s2;
        }
    }
}

// 1b) BN stats stage 2: reduce slices, fold into scale/shift.
__global__ void bn_stats2_kernel(const float* __restrict__ gamma,
                                 const float* __restrict__ beta) {
    const int c = blockIdx.x * blockDim.x + threadIdx.x;
    if (c >= CIN) return;
    double s = 0.0, s2 = 0.0;
    #pragma unroll
    for (int k = 0; k < NSLICE; ++k) {
        s  += g_part[(c * NSLICE + k) * 2 + 0];
        s2 += g_part[(c * NSLICE + k) * 2 + 1];
    }
    const double Nt = (double)NB * (double)HW;
    double mean = s / Nt;
    double var  = s2 / Nt - mean * mean;
    float rstd  = (float)(1.0 / sqrt(var + EPSC));
    float sc    = rstd * gamma[c];
    g_scale[c] = sc;
    g_shift[c] = beta[c] - (float)mean * sc;
}

// ---------------------------------------------------------------------------
// 2) Binarize + bit-pack activations: bit=1 iff BN(x) > 0.
// ---------------------------------------------------------------------------
__global__ void pack_x_kernel(const float* __restrict__ x) {
    const int idx = blockIdx.x * blockDim.x + threadIdx.x; // NB*8*HW threads
    if (idx >= NB * NWORDS * HW) return;
    const int s    = idx % HW;
    const int t    = idx / HW;
    const int word = t & 7;
    const int n    = t >> 3;
    const int cbase = word * 32;
    const float* p = x + ((size_t)(n * CIN + cbase)) * HW + s;
    unsigned int bits = 0;
    #pragma unroll
    for (int j = 0; j < 32; ++j) {
        float v  = p[(size_t)j * HW];
        float xh = fmaf(v, g_scale[cbase + j], g_shift[cbase + j]);
        if (xh > 0.0f) bits |= (1u << j);
    }
    g_xbits[((size_t)n * HW + s) * NWORDS + word] = bits;
}

// ---------------------------------------------------------------------------
// 3) Bit-pack weights + per-(co,tap) popcount table.
// ---------------------------------------------------------------------------
__global__ void pack_w_kernel(const float* __restrict__ w) {
    const int idx = blockIdx.x * blockDim.x + threadIdx.x; // COUT*9*8 = 18432
    if (idx >= COUT * TAPS * NWORDS) return;
    const int word = idx & 7;
    const int tap  = (idx >> 3) % TAPS;
    const int co   = idx / (TAPS * NWORDS);
    const float* p = w + ((size_t)co * CIN + word * 32) * TAPS + tap;
    unsigned int bits = 0;
    #pragma unroll
    for (int j = 0; j < 32; ++j)
        if (p[(size_t)j * TAPS] > 0.0f) bits |= (1u << j);
    g_wbits[co * WPC + tap * NWORDS + word] = bits;
    int pc = __popc(bits);
    #pragma unroll
    for (int o = 4; o > 0; o >>= 1)
        pc += __shfl_down_sync(0xffffffffu, pc, o, 8);
    if (word == 0) g_w9[co * TAPS + tap] = pc;
}

// ---------------------------------------------------------------------------
// 4) XNOR-popcount conv + bias + ReLU.
//    Block: 224 threads = (56 w) x (4 h rows) for one n; loops co by 2.
//    x window (72 words) in registers; weights (73 KB) in smem, read as uint4.
// ---------------------------------------------------------------------------
#define CONV_THREADS 224
#define SMEM_CONV ((COUT * WPC + COUT * TAPS + COUT) * 4)

__global__ void __launch_bounds__(CONV_THREADS, 2)
bconv_kernel(const float* __restrict__ bias, float* __restrict__ out) {
    extern __shared__ unsigned int smem[];
    unsigned int* s_w   = smem;                       // COUT*72
    int*          s_w9  = (int*)(smem + COUT * WPC);  // COUT*9
    float*        s_b   = (float*)(smem + COUT * WPC + COUT * TAPS); // COUT

    const int tid = threadIdx.x;
    {   // vectorized smem fill of weights
        const uint4* src = (const uint4*)g_wbits;
        uint4* dst = (uint4*)s_w;
        for (int i = tid; i < COUT * WPC / 4; i += CONV_THREADS) dst[i] = src[i];
    }
    for (int i = tid; i < COUT * TAPS; i += CONV_THREADS) s_w9[i] = g_w9[i];
    for (int i = tid; i < COUT; i += CONV_THREADS) s_b[i] = bias[i];
    __syncthreads();

    const int tx = tid % WWID;       // output w
    const int ty = tid / WWID;       // 0..3
    const int h  = blockIdx.x * 4 + ty;
    const int n  = blockIdx.y;

    const unsigned int* xb = g_xbits + (size_t)n * HW * NWORDS;

    unsigned int xr[WPC];
    unsigned int invmask = 0;
    #pragma unroll
    for (int dh = -1; dh <= 1; ++dh) {
        #pragma unroll
        for (int dw = -1; dw <= 1; ++dw) {
            const int tap = (dh + 1) * 3 + (dw + 1);
            const int hh = h + dh, ww = tx + dw;
            const bool valid = (hh >= 0) & (hh < HH) & (ww >= 0) & (ww < WWID);
            if (valid) {
                const uint4* p = (const uint4*)(xb + ((size_t)hh * WWID + ww) * NWORDS);
                uint4 a = p[0], b2 = p[1];
                xr[tap*8+0]=a.x;  xr[tap*8+1]=a.y;  xr[tap*8+2]=a.z;  xr[tap*8+3]=a.w;
                xr[tap*8+4]=b2.x; xr[tap*8+5]=b2.y; xr[tap*8+6]=b2.z; xr[tap*8+7]=b2.w;
            } else {
                invmask |= (1u << tap);
                #pragma unroll
                for (int k = 0; k < 8; ++k) xr[tap*8+k] = 0u;
            }
        }
    }
    const int nvalid = TAPS - __popc(invmask);
    const int base   = CIN * nvalid;

    // invalid-tap list (max 5) for border correction
    int itap[5]; int nitap = 0;
    {
        unsigned int m = invmask;
        while (m) { itap[nitap++] = __ffs(m) - 1; m &= m - 1; }
    }

    float* outp = out + (size_t)n * COUT * HW + h * WWID + tx;

    for (int co = 0; co < COUT; co += 2) {
        const uint4* wp0 = (const uint4*)(s_w + co * WPC);
        const uint4* wp1 = (const uint4*)(s_w + (co + 1) * WPC);
        int a0 = 0, a1 = 0, a2 = 0, a3 = 0;
        int c0 = 0, c1 = 0, c2 = 0, c3 = 0;
        #pragma unroll
        for (int t = 0; t < WPC / 4; ++t) {
            const uint4 w0 = wp0[t];
            const uint4 w1 = wp1[t];
            const unsigned int x0 = xr[4*t+0], x1 = xr[4*t+1];
            const unsigned int x2 = xr[4*t+2], x3 = xr[4*t+3];
            a0 += __popc(x0 ^ w0.x);
            a1 += __popc(x1 ^ w0.y);
            a2 += __popc(x2 ^ w0.z);
            a3 += __popc(x3 ^ w0.w);
            c0 += __popc(x0 ^ w1.x);
            c1 += __popc(x1 ^ w1.y);
            c2 += __popc(x2 ^ w1.z);
            c3 += __popc(x3 ^ w1.w);
        }
        int accA = (a0 + a1) + (a2 + a3);
        int accB = (c0 + c1) + (c2 + c3);
        int corA = 0, corB = 0;
        if (nitap) {
            for (int k = 0; k < nitap; ++k) {
                corA += s_w9[co * TAPS + itap[k]];
                corB += s_w9[(co + 1) * TAPS + itap[k]];
            }
        }
        float yA = (float)(base - 2 * accA + 2 * corA) + s_b[co];
        float yB = (float)(base - 2 * accB + 2 * corB) + s_b[co + 1];
        outp[(size_t)co * HW]       = fmaxf(yA, 0.0f);
        outp[(size_t)(co + 1) * HW] = fmaxf(yB, 0.0f);
    }
}

// ---------------------------------------------------------------------------
extern "C" void kernel_launch(void* const* d_in, const int* in_sizes, int n_in,
                              void* d_out, int out_size) {
    const float* x     = (const float*)d_in[0];
    const float* gamma = (const float*)d_in[1];
    const float* beta  = (const float*)d_in[2];
    const float* w     = (const float*)d_in[3];
    const float* b     = (const float*)d_in[4];
    float* out = (float*)d_out;

    dim3 sgrid(CIN, NSLICE);
    bn_stats1_kernel<<<sgrid, 256>>>(x);
    bn_stats2_kernel<<<1, 256>>>(gamma, beta);

    const int px_threads = NB * NWORDS * HW;
    pack_x_kernel<<<(px_threads + 255) / 256, 256>>>(x);

    pack_w_kernel<<<(COUT * TAPS * NWORDS + 255) / 256, 256>>>(w);

    cudaFuncSetAttribute(bconv_kernel,
                         cudaFuncAttributeMaxDynamicSharedMemorySize, SMEM_CONV);
    dim3 grid(HH / 4, NB);
    bconv_kernel<<<grid, CONV_THREADS, SMEM_CONV>>>(b, out);
}